// round 15
// baseline (speedup 1.0000x reference)
#include <cuda_runtime.h>
#include <cuda_fp16.h>
#include <math.h>

#define D 32
#define HP 16            // half-plane width (dims per edge pass)
#define F 64
#define MAXB 262144
#define MAXNE 500000

// Scratch (device globals — no allocation allowed)
__device__ float g_agg_user[MAXB * D];        // seeded with h_user, edges add in
__device__ float g_agg_item[MAXB * D];        // seeded with h_item
__device__ __half g_hh_user[2 * MAXB * HP];   // fp16 h planes for edge gather
__device__ __half g_hh_item[2 * MAXB * HP];
__device__ __half g_proj_ui[2 * MAXNE * HP];  // fp16 proj planes
__device__ __half g_proj_iu[2 * MAXNE * HP];

// ---------------------------------------------------------------------------
// mma.m16n8k16 fp16 -> fp32 helper
// ---------------------------------------------------------------------------
__device__ __forceinline__ void mma_16816(float* c, unsigned a0, unsigned a1,
                                          unsigned a2, unsigned a3,
                                          unsigned b0, unsigned b1) {
    asm volatile(
        "mma.sync.aligned.m16n8k16.row.col.f32.f16.f16.f32 "
        "{%0,%1,%2,%3}, {%4,%5,%6,%7}, {%8,%9}, {%0,%1,%2,%3};"
        : "+f"(c[0]), "+f"(c[1]), "+f"(c[2]), "+f"(c[3])
        : "r"(a0), "r"(a1), "r"(a2), "r"(a3), "r"(b0), "r"(b1));
}

// split float pair into fp16 hi + fp16 lo residual
__device__ __forceinline__ void split_h2(float x, float y,
                                         unsigned& hi, unsigned& lo) {
    __half hx = __float2half_rn(x);
    __half hy = __float2half_rn(y);
    __half lx = __float2half_rn(x - __half2float(hx));
    __half ly = __float2half_rn(y - __half2float(hy));
    __half2 h = __halves2half2(hx, hy);
    __half2 l = __halves2half2(lx, ly);
    hi = *(unsigned*)&h;
    lo = *(unsigned*)&l;
}

// ---------------------------------------------------------------------------
// Kernel 1: h = mem[ids] @ W on TENSOR CORES (3-pass hi/lo: exact to ~2^-21).
// Block = 256 threads handles 256 nodes; user then item phase (smem reused).
// Writes fp32 agg seed + fp16 plane-major h tables.
// ---------------------------------------------------------------------------
__global__ void k_h(const float* __restrict__ mem_user,
                    const float* __restrict__ mem_item,
                    const int* __restrict__ nid_user,
                    const int* __restrict__ nid_item,
                    const float* __restrict__ Wu,
                    const float* __restrict__ Wi,
                    int B) {
    __shared__ __half sM[256 * 40];     // gathered mem rows, fp16 hi
    __shared__ __half sMlo[256 * 40];   // fp16 lo residual
    __shared__ __half sWT[32 * 40];     // W^T [n][k] hi (one type at a time)
    __shared__ __half sWTlo[32 * 40];   // W^T lo
    __shared__ int sIds[512];           // user ids [0..255], item ids [256..511]

    int tid = threadIdx.x;
    int n0 = blockIdx.x * 256;
    int lane = tid & 31;
    int warp = tid >> 5;
    int g = lane >> 2;
    int tig = lane & 3;

    {
        int node = n0 + tid;
        sIds[tid] = (node < B) ? nid_user[node] : 0;
        sIds[256 + tid] = (node < B) ? nid_item[node] : 0;
    }

    for (int type = 0; type < 2; type++) {
        const float* mem = type ? mem_item : mem_user;
        const float* W = type ? Wi : Wu;
        float* agg = type ? g_agg_item : g_agg_user;
        __half* hh = type ? g_hh_item : g_hh_user;

        __syncthreads();   // ids ready (iter0) / prev mma done reading smem

        for (int i = tid; i < 32 * 32; i += 256) {
            int k = i >> 5;
            int n = i & 31;
            float v = W[k * 32 + n];
            __half hi = __float2half_rn(v);
            sWT[n * 40 + k] = hi;
            sWTlo[n * 40 + k] = __float2half_rn(v - __half2float(hi));
        }

        for (int it = 0; it < 8; it++) {
            int idx = tid + it * 256;
            int row = idx >> 3;
            int c = idx & 7;
            int nid = sIds[type * 256 + row];
            float4 v = *(const float4*)(mem + (size_t)nid * D + c * 4);
            uint2 ph, pl;
            split_h2(v.x, v.y, ph.x, pl.x);
            split_h2(v.z, v.w, ph.y, pl.y);
            *(uint2*)(sM + row * 40 + c * 4) = ph;
            *(uint2*)(sMlo + row * 40 + c * 4) = pl;
        }
        __syncthreads();

        float acc[2][4][4];
#pragma unroll
        for (int m = 0; m < 2; m++)
#pragma unroll
            for (int nt = 0; nt < 4; nt++)
#pragma unroll
                for (int j = 0; j < 4; j++) acc[m][nt][j] = 0.f;

#pragma unroll
        for (int pass = 0; pass < 3; pass++) {
            const unsigned* Aw = (const unsigned*)(pass == 1 ? sMlo : sM);
            const unsigned* Ww = (const unsigned*)(pass == 2 ? sWTlo : sWT);
#pragma unroll
            for (int m = 0; m < 2; m++) {
                int rb = warp * 32 + m * 16 + g;
#pragma unroll
                for (int ks = 0; ks < 2; ks++) {
                    unsigned a0 = Aw[rb * 20 + ks * 8 + tig];
                    unsigned a1 = Aw[(rb + 8) * 20 + ks * 8 + tig];
                    unsigned a2 = Aw[rb * 20 + ks * 8 + tig + 4];
                    unsigned a3 = Aw[(rb + 8) * 20 + ks * 8 + tig + 4];
#pragma unroll
                    for (int nt = 0; nt < 4; nt++) {
                        unsigned b0 = Ww[(nt * 8 + g) * 20 + ks * 8 + tig];
                        unsigned b1 = Ww[(nt * 8 + g) * 20 + ks * 8 + tig + 4];
                        mma_16816(acc[m][nt], a0, a1, a2, a3, b0, b1);
                    }
                }
            }
        }

#pragma unroll
        for (int m = 0; m < 2; m++) {
            int rA = warp * 32 + m * 16 + g;
            int rB = rA + 8;
            int nodeA = n0 + rA;
            int nodeB = n0 + rB;
#pragma unroll
            for (int nt = 0; nt < 4; nt++) {
                int col = nt * 8 + 2 * tig;      // even
                int plane = col >> 4;
                int off = col & 15;
                float c0 = acc[m][nt][0], c1 = acc[m][nt][1];
                float c2 = acc[m][nt][2], c3 = acc[m][nt][3];
                if (nodeA < B) {
                    *(float2*)(agg + (size_t)nodeA * D + col) = make_float2(c0, c1);
                    *(__half2*)(hh + ((size_t)plane * MAXB + nodeA) * HP + off) =
                        __floats2half2_rn(c0, c1);
                }
                if (nodeB < B) {
                    *(float2*)(agg + (size_t)nodeB * D + col) = make_float2(c2, c3);
                    *(__half2*)(hh + ((size_t)plane * MAXB + nodeB) * HP + off) =
                        __floats2half2_rn(c2, c3);
                }
            }
        }
    }
}

// ---------------------------------------------------------------------------
// Kernel 2: proj = feat @ We + be for BOTH edge types, tensor cores.
// Tile: 128 rows x 64 cols (cols 0..31 -> ui, 32..63 -> iu), K=64.
// Epilogue: stage fp16 tile in smem, coalesced 16B plane-major writeout.
// ---------------------------------------------------------------------------
__global__ void k_proj(const float* __restrict__ feat,
                       const float* __restrict__ We0, const float* __restrict__ be0,
                       const float* __restrict__ We1, const float* __restrict__ be1,
                       int NE) {
    __shared__ __half sA[128 * 72];      // feat fp16 [row][k]; reused as out tile
    __shared__ __half sWT[64 * 72];      // [n][k]
    __shared__ float sb[64];

    int tid = threadIdx.x;
    int row0 = blockIdx.x * 128;

    for (int i = tid; i < 64 * 64; i += 256) {
        int k = i >> 6;
        int n = i & 63;
        float v = (n < 32) ? We0[k * 32 + n] : We1[k * 32 + (n - 32)];
        sWT[n * 72 + k] = __float2half_rn(v);
    }
    if (tid < 32) { sb[tid] = be0[tid]; sb[32 + tid] = be1[tid]; }

    for (int i = tid; i < 128 * 16; i += 256) {
        int r = i >> 4;
        int k0 = (i & 15) * 4;
        int gr = row0 + r;
        float4 v = make_float4(0.f, 0.f, 0.f, 0.f);
        if (gr < NE) v = *(const float4*)(feat + (size_t)gr * F + k0);
        __half2 h01 = __floats2half2_rn(v.x, v.y);
        __half2 h23 = __floats2half2_rn(v.z, v.w);
        uint2 pk;
        pk.x = *(unsigned*)&h01;
        pk.y = *(unsigned*)&h23;
        *(uint2*)(sA + r * 72 + k0) = pk;
    }
    __syncthreads();

    int lane = tid & 31;
    int warp = tid >> 5;
    int g = lane >> 2;       // 0..7
    int tig = lane & 3;      // 0..3

    const unsigned* Aw = (const unsigned*)sA;    // 36 words per row
    const unsigned* Ww = (const unsigned*)sWT;   // 36 words per n

    float acc[8][4];
#pragma unroll
    for (int t = 0; t < 8; t++) {
        float bc0 = sb[t * 8 + 2 * tig];
        float bc1 = sb[t * 8 + 2 * tig + 1];
        acc[t][0] = bc0; acc[t][1] = bc1; acc[t][2] = bc0; acc[t][3] = bc1;
    }

    int r0 = warp * 16 + g;
#pragma unroll
    for (int ks = 0; ks < 4; ks++) {
        unsigned a0 = Aw[r0 * 36 + ks * 8 + tig];
        unsigned a1 = Aw[(r0 + 8) * 36 + ks * 8 + tig];
        unsigned a2 = Aw[r0 * 36 + ks * 8 + tig + 4];
        unsigned a3 = Aw[(r0 + 8) * 36 + ks * 8 + tig + 4];
#pragma unroll
        for (int t = 0; t < 8; t++) {
            unsigned b0 = Ww[(t * 8 + g) * 36 + ks * 8 + tig];
            unsigned b1 = Ww[(t * 8 + g) * 36 + ks * 8 + tig + 4];
            mma_16816(acc[t], a0, a1, a2, a3, b0, b1);
        }
    }
    __syncthreads();   // everyone done reading sA before it becomes the out tile

    int rA = warp * 16 + g;
    int rB = rA + 8;
#pragma unroll
    for (int t = 0; t < 8; t++) {
        int col = t * 8 + 2 * tig;   // even -> 4B aligned
        *(__half2*)(sA + rA * 72 + col) = __floats2half2_rn(acc[t][0], acc[t][1]);
        *(__half2*)(sA + rB * 72 + col) = __floats2half2_rn(acc[t][2], acc[t][3]);
    }
    __syncthreads();

    for (int i = tid; i < 1024; i += 256) {
        int r = i & 127;             // row within tile
        int c8 = i >> 7;             // 0..7 : which 8-half chunk
        int col = c8 * 8;            // source col in tile (0..56)
        int gr = row0 + r;
        if (gr >= NE) continue;
        uint4 v = *(const uint4*)(sA + r * 72 + col);
        __half* base = (col < 32) ? g_proj_ui : g_proj_iu;
        int c = col & 31;
        int plane = c >> 4;
        int off = c & 15;
        *(uint4*)(base + ((size_t)plane * MAXNE + gr) * HP + off) = v;
    }
}

// ---------------------------------------------------------------------------
// Kernel 3: per-edge message + scatter for ONE dim-plane (16 dims).
// 4 lanes per edge, lane handles 4 dims -> one red.global.add.v4.f32.
// Two sequential plane launches keep the per-pass working set inside L2.
// ---------------------------------------------------------------------------
__global__ void k_edge(const int* __restrict__ src_ui, const int* __restrict__ dst_ui,
                       const int* __restrict__ idx_ui, const float* __restrict__ t_ui,
                       const int* __restrict__ src_iu, const int* __restrict__ dst_iu,
                       const int* __restrict__ idx_iu, const float* __restrict__ t_iu,
                       const float* __restrict__ time_w, const float* __restrict__ time_b,
                       int E, int plane) {
    int tid = threadIdx.x;
    int lane = tid & 31;
    int warp = tid >> 5;
    int q = lane & 3;        // dim quad within the 16-dim plane
    int s = lane >> 2;       // edge slot within warp (0..7)
    long e = (long)blockIdx.x * 64 + warp * 8 + s;
    if (e >= 2L * E) return;

    const int *srcA, *dstA, *idxA;
    const float* tA;
    const __half* hh;
    const __half* proj;
    float* agg;
    int ei;
    if (e < E) {
        ei = (int)e;
        srcA = src_ui; dstA = dst_ui; idxA = idx_ui; tA = t_ui;
        hh = g_hh_user; proj = g_proj_ui; agg = g_agg_item;
    } else {
        ei = (int)(e - E);
        srcA = src_iu; dstA = dst_iu; idxA = idx_iu; tA = t_iu;
        hh = g_hh_item; proj = g_proj_iu; agg = g_agg_user;
    }
    int srch = srcA[ei];
    int dst = dstA[ei];
    int fid = idxA[ei];
    float t = tA[ei];

    const __half2* hp = (const __half2*)(hh + ((size_t)plane * MAXB + srch) * HP + q * 4);
    float2 h01 = __half22float2(hp[0]);
    float2 h23 = __half22float2(hp[1]);
    const __half2* pp = (const __half2*)(proj + ((size_t)plane * MAXNE + fid) * HP + q * 4);
    float2 p01 = __half22float2(pp[0]);
    float2 p23 = __half22float2(pp[1]);
    int dq = plane * HP + q * 4;
    float4 tw = *(const float4*)(time_w + dq);
    float4 tb = *(const float4*)(time_b + dq);

    float m0 = h01.x + p01.x + __cosf(fmaf(t, tw.x, tb.x));
    float m1 = h01.y + p01.y + __cosf(fmaf(t, tw.y, tb.y));
    float m2 = h23.x + p23.x + __cosf(fmaf(t, tw.z, tb.z));
    float m3 = h23.y + p23.y + __cosf(fmaf(t, tw.w, tb.w));

    float* p = agg + (size_t)dst * D + dq;
    asm volatile("red.global.add.v4.f32 [%0], {%1, %2, %3, %4};"
                 :: "l"(p), "f"(m0), "f"(m1), "f"(m2), "f"(m3) : "memory");
}

// ---------------------------------------------------------------------------
// Kernel 4: z = relu(agg) staged fp16 hi+lo; layer-1 GEMM on tensor cores
// (2 passes); layer-2 on tensor cores with EXACT hi/lo on BOTH operands
// (x1 split from registers, W2 staged hi+lo -> 3 passes); layer-3 dot+shfl.
// ---------------------------------------------------------------------------
__global__ void k_final(const float* __restrict__ W1, const float* __restrict__ b1,
                        const float* __restrict__ W2, const float* __restrict__ b2,
                        const float* __restrict__ W3, const float* __restrict__ b3,
                        float* __restrict__ out, int B) {
    __shared__ __half sA[128 * 72];     // z hi [node][k]
    __shared__ __half sAlo[128 * 72];   // z lo
    __shared__ __half sW1T[64 * 72];    // [n][k]
    __shared__ __half sW2T[16 * 72];    // [n][k] hi
    __shared__ __half sW2Tlo[16 * 72];  // [n][k] lo
    __shared__ float sW3[16];
    __shared__ float sb1[64];
    __shared__ float sb2[16];
    __shared__ float sb3;

    int tid = threadIdx.x;
    int n0 = blockIdx.x * 128;

    for (int i = tid; i < 64 * 64; i += 256) {
        int k = i >> 6;
        int n = i & 63;
        sW1T[n * 72 + k] = __float2half_rn(W1[k * 64 + n]);
    }
    for (int i = tid; i < 16 * 64; i += 256) {
        int n = i >> 6;
        int k = i & 63;
        float v = W2[k * 16 + n];
        __half hi = __float2half_rn(v);
        sW2T[n * 72 + k] = hi;
        sW2Tlo[n * 72 + k] = __float2half_rn(v - __half2float(hi));
    }
    if (tid < 16) { sW3[tid] = W3[tid]; sb2[tid] = b2[tid]; }
    if (tid < 64) sb1[tid] = b1[tid];
    if (tid == 0) sb3 = b3[0];

    // stage z = relu(agg) as fp16 hi + lo
    for (int i = tid; i < 128 * 16; i += 256) {
        int n = i >> 4;
        int kc = i & 15;
        int node = n0 + n;
        float4 v = make_float4(0.f, 0.f, 0.f, 0.f);
        if (node < B) {
            v = (kc < 8) ? *(const float4*)(g_agg_user + (size_t)node * D + kc * 4)
                         : *(const float4*)(g_agg_item + (size_t)node * D + (kc - 8) * 4);
        }
        v.x = fmaxf(v.x, 0.f); v.y = fmaxf(v.y, 0.f);
        v.z = fmaxf(v.z, 0.f); v.w = fmaxf(v.w, 0.f);
        uint2 ph, pl;
        split_h2(v.x, v.y, ph.x, pl.x);
        split_h2(v.z, v.w, ph.y, pl.y);
        *(uint2*)(sA + n * 72 + kc * 4) = ph;
        *(uint2*)(sAlo + n * 72 + kc * 4) = pl;
    }
    __syncthreads();

    int lane = tid & 31;
    int warp = tid >> 5;
    int g = lane >> 2;
    int tig = lane & 3;

    const unsigned* Ww = (const unsigned*)sW1T;

    // layer 1: acc[t] covers (rows warp*16+g, +8) x (cols t*8+2tig, +1)
    float acc[8][4];
#pragma unroll
    for (int t = 0; t < 8; t++) {
        float bc0 = sb1[t * 8 + 2 * tig];
        float bc1 = sb1[t * 8 + 2 * tig + 1];
        acc[t][0] = bc0; acc[t][1] = bc1; acc[t][2] = bc0; acc[t][3] = bc1;
    }

    int r0 = warp * 16 + g;
#pragma unroll
    for (int pass = 0; pass < 2; pass++) {
        const unsigned* Aw = (const unsigned*)(pass ? sAlo : sA);
#pragma unroll
        for (int ks = 0; ks < 4; ks++) {
            unsigned a0 = Aw[r0 * 36 + ks * 8 + tig];
            unsigned a1 = Aw[(r0 + 8) * 36 + ks * 8 + tig];
            unsigned a2 = Aw[r0 * 36 + ks * 8 + tig + 4];
            unsigned a3 = Aw[(r0 + 8) * 36 + ks * 8 + tig + 4];
#pragma unroll
            for (int t = 0; t < 8; t++) {
                unsigned b0 = Ww[(t * 8 + g) * 36 + ks * 8 + tig];
                unsigned b1 = Ww[(t * 8 + g) * 36 + ks * 8 + tig + 4];
                mma_16816(acc[t], a0, a1, a2, a3, b0, b1);
            }
        }
    }

    // layer 2: x1 = relu(acc) as hi/lo A-frags; W2 hi/lo B-frags (3 passes)
    float acc2[2][4];
#pragma unroll
    for (int nt = 0; nt < 2; nt++) {
        float bc0 = sb2[nt * 8 + 2 * tig];
        float bc1 = sb2[nt * 8 + 2 * tig + 1];
        acc2[nt][0] = bc0; acc2[nt][1] = bc1; acc2[nt][2] = bc0; acc2[nt][3] = bc1;
    }
    const unsigned* W2w = (const unsigned*)sW2T;
    const unsigned* W2lw = (const unsigned*)sW2Tlo;
#pragma unroll
    for (int j = 0; j < 4; j++) {
        unsigned a0h, a0l, a1h, a1l, a2h, a2l, a3h, a3l;
        split_h2(fmaxf(acc[2 * j][0], 0.f), fmaxf(acc[2 * j][1], 0.f), a0h, a0l);
        split_h2(fmaxf(acc[2 * j][2], 0.f), fmaxf(acc[2 * j][3], 0.f), a1h, a1l);
        split_h2(fmaxf(acc[2 * j + 1][0], 0.f), fmaxf(acc[2 * j + 1][1], 0.f), a2h, a2l);
        split_h2(fmaxf(acc[2 * j + 1][2], 0.f), fmaxf(acc[2 * j + 1][3], 0.f), a3h, a3l);
#pragma unroll
        for (int nt = 0; nt < 2; nt++) {
            unsigned b0 = W2w[(nt * 8 + g) * 36 + j * 8 + tig];
            unsigned b1 = W2w[(nt * 8 + g) * 36 + j * 8 + tig + 4];
            unsigned b0l = W2lw[(nt * 8 + g) * 36 + j * 8 + tig];
            unsigned b1l = W2lw[(nt * 8 + g) * 36 + j * 8 + tig + 4];
            mma_16816(acc2[nt], a0h, a1h, a2h, a3h, b0, b1);
            mma_16816(acc2[nt], a0l, a1l, a2l, a3l, b0, b1);
            mma_16816(acc2[nt], a0h, a1h, a2h, a3h, b0l, b1l);
        }
    }

    // layer 3: per-lane partial dot over cols (nt*8+2tig, +1), reduce over tig
    float pA = 0.f, pB = 0.f;
#pragma unroll
    for (int nt = 0; nt < 2; nt++) {
        int c = nt * 8 + 2 * tig;
        pA += fmaxf(acc2[nt][0], 0.f) * sW3[c] + fmaxf(acc2[nt][1], 0.f) * sW3[c + 1];
        pB += fmaxf(acc2[nt][2], 0.f) * sW3[c] + fmaxf(acc2[nt][3], 0.f) * sW3[c + 1];
    }
    pA += __shfl_xor_sync(0xffffffffu, pA, 1);
    pA += __shfl_xor_sync(0xffffffffu, pA, 2);
    pB += __shfl_xor_sync(0xffffffffu, pB, 1);
    pB += __shfl_xor_sync(0xffffffffu, pB, 2);
    if (tig == 0) {
        int nodeA = n0 + warp * 16 + g;
        int nodeB = nodeA + 8;
        if (nodeA < B) out[nodeA] = pA + sb3;
        if (nodeB < B) out[nodeB] = pB + sb3;
    }
}

// ---------------------------------------------------------------------------
// Launch. k_h runs on a side stream concurrently with k_proj (fork/join via
// events; streams/events created once, outside any captured region).
// ---------------------------------------------------------------------------
extern "C" void kernel_launch(void* const* d_in, const int* in_sizes, int n_in,
                              void* d_out, int out_size) {
    bool refOrder = in_sizes[2] > 1000000;

    int iMemU, iMemI, iFeat, iTui, iTiu, iWu, iWi, iWeUI, iBeUI, iWeIU, iBeIU;
    int iTw, iTb, iW1, iB1, iW2, iB2, iW3, iB3;
    int iNidU, iNidI, iSrcUI, iDstUI, iSrcIU, iDstIU, iIdxUI, iIdxIU;

    if (refOrder) {
        iMemU = 0;  iMemI = 1;  iFeat = 2;  iTui = 3;  iTiu = 4;
        iWu = 5;    iWi = 6;    iWeUI = 7;  iBeUI = 8; iWeIU = 9; iBeIU = 10;
        iTw = 11;   iTb = 12;
        iW1 = 13;   iB1 = 14;   iW2 = 15;   iB2 = 16;  iW3 = 17;  iB3 = 18;
        iNidU = 19; iNidI = 20;
        iSrcUI = 21; iDstUI = 22; iSrcIU = 23; iDstIU = 24; iIdxUI = 25; iIdxIU = 26;
    } else {
        iMemU = 0;  iMemI = 1;  iNidU = 2;  iNidI = 3;
        iSrcUI = 4; iDstUI = 5; iSrcIU = 6; iDstIU = 7; iIdxUI = 8; iIdxIU = 9;
        iTui = 10;  iTiu = 11;  iFeat = 12;
        iWu = 13;   iWi = 14;   iWeUI = 15; iBeUI = 16; iWeIU = 17; iBeIU = 18;
        iTw = 19;   iTb = 20;
        iW1 = 21;   iB1 = 22;   iW2 = 23;   iB2 = 24;   iW3 = 25;  iB3 = 26;
    }

    const float* mem_user = (const float*)d_in[iMemU];
    const float* mem_item = (const float*)d_in[iMemI];
    const float* feat     = (const float*)d_in[iFeat];
    const float* t_ui     = (const float*)d_in[iTui];
    const float* t_iu     = (const float*)d_in[iTiu];
    const float* Wu       = (const float*)d_in[iWu];
    const float* Wi       = (const float*)d_in[iWi];
    const float* WeUI     = (const float*)d_in[iWeUI];
    const float* beUI     = (const float*)d_in[iBeUI];
    const float* WeIU     = (const float*)d_in[iWeIU];
    const float* beIU     = (const float*)d_in[iBeIU];
    const float* tw       = (const float*)d_in[iTw];
    const float* tb       = (const float*)d_in[iTb];
    const float* W1       = (const float*)d_in[iW1];
    const float* b1       = (const float*)d_in[iB1];
    const float* W2       = (const float*)d_in[iW2];
    const float* b2       = (const float*)d_in[iB2];
    const float* W3       = (const float*)d_in[iW3];
    const float* b3       = (const float*)d_in[iB3];
    const int* nid_user   = (const int*)d_in[iNidU];
    const int* nid_item   = (const int*)d_in[iNidI];
    const int* src_ui     = (const int*)d_in[iSrcUI];
    const int* dst_ui     = (const int*)d_in[iDstUI];
    const int* src_iu     = (const int*)d_in[iSrcIU];
    const int* dst_iu     = (const int*)d_in[iDstIU];
    const int* idx_ui     = (const int*)d_in[iIdxUI];
    const int* idx_iu     = (const int*)d_in[iIdxIU];

    int B  = in_sizes[iNidU];
    int E  = in_sizes[iSrcUI];
    int NE = in_sizes[iFeat] / F;

    // one-time side stream + events (created outside any capture)
    static cudaStream_t s_side = nullptr;
    static cudaEvent_t ev_fork = nullptr, ev_join = nullptr;
    if (s_side == nullptr) {
        cudaStreamCreateWithFlags(&s_side, cudaStreamNonBlocking);
        cudaEventCreateWithFlags(&ev_fork, cudaEventDisableTiming);
        cudaEventCreateWithFlags(&ev_join, cudaEventDisableTiming);
    }

    // fork: k_h on side stream, k_proj on main; join before k_edge
    cudaEventRecord(ev_fork, 0);
    cudaStreamWaitEvent(s_side, ev_fork, 0);

    k_h<<<(B + 255) / 256, 256, 0, s_side>>>(mem_user, mem_item,
                                             nid_user, nid_item, Wu, Wi, B);
    cudaEventRecord(ev_join, s_side);

    k_proj<<<(NE + 127) / 128, 256>>>(feat, WeUI, beUI, WeIU, beIU, NE);

    cudaStreamWaitEvent(0, ev_join, 0);

    long total_edges = 2L * E;
    int nb_e = (int)((total_edges + 63) / 64);
    k_edge<<<nb_e, 256>>>(src_ui, dst_ui, idx_ui, t_ui,
                          src_iu, dst_iu, idx_iu, t_iu,
                          tw, tb, E, 0);
    k_edge<<<nb_e, 256>>>(src_ui, dst_ui, idx_ui, t_ui,
                          src_iu, dst_iu, idx_iu, t_iu,
                          tw, tb, E, 1);

    k_final<<<(B + 127) / 128, 256>>>(W1, b1, W2, b2, W3, b3,
                                      (float*)d_out, B);
}